// round 14
// baseline (speedup 1.0000x reference)
#include <cuda_runtime.h>
#include <cuda_fp16.h>
#include <cuda_fp8.h>
#include <math.h>
#include <stdint.h>

#define N_TOTAL 8192
#define HALF_N  4096
#define BM      128
#define BN      128
#define MTILES  64               // N_TOTAL / BM
#define NCTAS   152              // 1 per SM, persistent
#define THREADS 512
#define PITCHB  144              // 128B fp8 row + 16B pad

#define SMEM_A    0
#define SMEM_B0   18432
#define SMEM_B1   36864
#define SMEM_NI   55296
#define SMEM_NJ0  55808
#define SMEM_NJ1  56320
#define SMEM_TOTAL 56832

__device__ __align__(16) uint8_t g_Y[N_TOTAL * 128];   // 1 MB e4m3 copy
__device__ float g_norm[N_TOTAL];
__device__ float g_rowsum[N_TOTAL];
__device__ float g_diag[HALF_N];

// ---------------------------------------------------------------- helpers
__device__ __forceinline__ uint32_t smem_u32(const void* p) {
    uint32_t a;
    asm("{ .reg .u64 t; cvta.to.shared.u64 t, %1; cvt.u32.u64 %0, t; }"
        : "=r"(a) : "l"(p));
    return a;
}
__device__ __forceinline__ void cp_async16(uint32_t dst, const void* src) {
    asm volatile("cp.async.cg.shared.global [%0], [%1], 16;"
                 :: "r"(dst), "l"(src) : "memory");
}
__device__ __forceinline__ void cp_commit() {
    asm volatile("cp.async.commit_group;" ::: "memory");
}
template <int N>
__device__ __forceinline__ void cp_wait() {
    asm volatile("cp.async.wait_group %0;" :: "n"(N) : "memory");
}
__device__ __forceinline__ void mma_fp8(float* c, const uint32_t* a, const uint32_t* b) {
    asm volatile(
        "mma.sync.aligned.m16n8k32.row.col.f32.e4m3.e4m3.f32 "
        "{%0,%1,%2,%3}, {%4,%5,%6,%7}, {%8,%9}, {%0,%1,%2,%3};"
        : "+f"(c[0]), "+f"(c[1]), "+f"(c[2]), "+f"(c[3])
        : "r"(a[0]), "r"(a[1]), "r"(a[2]), "r"(a[3]), "r"(b[0]), "r"(b[1]));
}
__device__ __forceinline__ void ldsm_x4(uint32_t* r, uint32_t addr) {
    asm volatile("ldmatrix.sync.aligned.m8n8.x4.shared.b16 {%0,%1,%2,%3}, [%4];"
                 : "=r"(r[0]), "=r"(r[1]), "=r"(r[2]), "=r"(r[3])
                 : "r"(addr));
}

// ---------------------------------------------------------------------------
// Kernel 1: prep at MLP=4 — each warp handles 2 row-pairs (4 rows).
// ---------------------------------------------------------------------------
__global__ void prep_kernel(const float* __restrict__ X) {
    int w2 = (blockIdx.x * blockDim.x + threadIdx.x) >> 5;
    int lane = threadIdx.x & 31;
    if (w2 >= HALF_N / 2) return;
    const int p0 = 2 * w2, p1 = 2 * w2 + 1;
    const float4* X4 = (const float4*)X;

    float4 v0 = X4[(size_t)p0 * 32 + lane];
    float4 u0 = X4[(size_t)(p0 + HALF_N) * 32 + lane];
    float4 v1 = X4[(size_t)p1 * 32 + lane];
    float4 u1 = X4[(size_t)(p1 + HALF_N) * 32 + lane];

    float sv0 = v0.x * v0.x + v0.y * v0.y + v0.z * v0.z + v0.w * v0.w;
    float su0 = u0.x * u0.x + u0.y * u0.y + u0.z * u0.z + u0.w * u0.w;
    float sv1 = v1.x * v1.x + v1.y * v1.y + v1.z * v1.z + v1.w * v1.w;
    float su1 = u1.x * u1.x + u1.y * u1.y + u1.z * u1.z + u1.w * u1.w;
    float d0x = v0.x - u0.x, d0y = v0.y - u0.y, d0z = v0.z - u0.z, d0w = v0.w - u0.w;
    float d1x = v1.x - u1.x, d1y = v1.y - u1.y, d1z = v1.z - u1.z, d1w = v1.w - u1.w;
    float q0 = d0x * d0x + d0y * d0y + d0z * d0z + d0w * d0w;
    float q1 = d1x * d1x + d1y * d1y + d1z * d1z + d1w * d1w;
    #pragma unroll
    for (int off = 16; off; off >>= 1) {
        sv0 += __shfl_xor_sync(0xffffffffu, sv0, off);
        su0 += __shfl_xor_sync(0xffffffffu, su0, off);
        sv1 += __shfl_xor_sync(0xffffffffu, sv1, off);
        su1 += __shfl_xor_sync(0xffffffffu, su1, off);
        q0  += __shfl_xor_sync(0xffffffffu, q0, off);
        q1  += __shfl_xor_sync(0xffffffffu, q1, off);
    }
    if (lane == 0) {
        g_norm[p0] = sv0;          g_norm[p1] = sv1;
        g_norm[p0 + HALF_N] = su0; g_norm[p1 + HALF_N] = su1;
        g_rowsum[p0] = 0.0f;           g_rowsum[p1] = 0.0f;
        g_rowsum[p0 + HALF_N] = 0.0f;  g_rowsum[p1 + HALF_N] = 0.0f;
        g_diag[p0] = 1.0f / (fmaxf(q0, 0.0f) + 1.0f);
        g_diag[p1] = 1.0f / (fmaxf(q1, 0.0f) + 1.0f);
    }

    {
        uint32_t b0 = __nv_cvt_float_to_fp8(v0.x, __NV_SATFINITE, __NV_E4M3);
        uint32_t b1 = __nv_cvt_float_to_fp8(v0.y, __NV_SATFINITE, __NV_E4M3);
        uint32_t b2 = __nv_cvt_float_to_fp8(v0.z, __NV_SATFINITE, __NV_E4M3);
        uint32_t b3 = __nv_cvt_float_to_fp8(v0.w, __NV_SATFINITE, __NV_E4M3);
        ((uint32_t*)(g_Y + (size_t)p0 * 128))[lane] = b0 | (b1 << 8) | (b2 << 16) | (b3 << 24);
    }
    {
        uint32_t b0 = __nv_cvt_float_to_fp8(u0.x, __NV_SATFINITE, __NV_E4M3);
        uint32_t b1 = __nv_cvt_float_to_fp8(u0.y, __NV_SATFINITE, __NV_E4M3);
        uint32_t b2 = __nv_cvt_float_to_fp8(u0.z, __NV_SATFINITE, __NV_E4M3);
        uint32_t b3 = __nv_cvt_float_to_fp8(u0.w, __NV_SATFINITE, __NV_E4M3);
        ((uint32_t*)(g_Y + (size_t)(p0 + HALF_N) * 128))[lane] = b0 | (b1 << 8) | (b2 << 16) | (b3 << 24);
    }
    {
        uint32_t b0 = __nv_cvt_float_to_fp8(v1.x, __NV_SATFINITE, __NV_E4M3);
        uint32_t b1 = __nv_cvt_float_to_fp8(v1.y, __NV_SATFINITE, __NV_E4M3);
        uint32_t b2 = __nv_cvt_float_to_fp8(v1.z, __NV_SATFINITE, __NV_E4M3);
        uint32_t b3 = __nv_cvt_float_to_fp8(v1.w, __NV_SATFINITE, __NV_E4M3);
        ((uint32_t*)(g_Y + (size_t)p1 * 128))[lane] = b0 | (b1 << 8) | (b2 << 16) | (b3 << 24);
    }
    {
        uint32_t b0 = __nv_cvt_float_to_fp8(u1.x, __NV_SATFINITE, __NV_E4M3);
        uint32_t b1 = __nv_cvt_float_to_fp8(u1.y, __NV_SATFINITE, __NV_E4M3);
        uint32_t b2 = __nv_cvt_float_to_fp8(u1.z, __NV_SATFINITE, __NV_E4M3);
        uint32_t b3 = __nv_cvt_float_to_fp8(u1.w, __NV_SATFINITE, __NV_E4M3);
        ((uint32_t*)(g_Y + (size_t)(p1 + HALF_N) * 128))[lane] = b0 | (b1 << 8) | (b2 << 16) | (b3 << 24);
    }
}

__device__ __forceinline__ void adv(int& bi, int& bj) {
    if (bj == MTILES - 1) { ++bi; bj = bi; } else ++bj;
}
__device__ __forceinline__ void load_tile(uint32_t dst, int blk, int tid) {
    const char* Yb = (const char*)g_Y;
    #pragma unroll
    for (int i2 = 0; i2 < 2; ++i2) {
        int chunk = i2 * THREADS + tid;        // 1024 chunks
        int r = chunk >> 3, cc = chunk & 7;
        cp_async16(dst + r * PITCHB + cc * 16,
                   Yb + (size_t)(blk * 128 + r) * 128 + cc * 16);
    }
}

// ---------------------------------------------------------------------------
// Kernel 2: persistent triangular fp8 GEMM. 512 threads, 16 warps as 4x4,
// warp tile 32x32 (acc = 32 regs -> no spills). Double-buffered B, one
// barrier per tile, exact diagonal override. 1 CTA/SM, grid 152.
// ---------------------------------------------------------------------------
__global__ void __launch_bounds__(THREADS, 1)
simsum_kernel() {
    extern __shared__ char smem[];
    const uint32_t sb = smem_u32(smem);
    float* nIs = (float*)(smem + SMEM_NI);

    const int tid = threadIdx.x;
    const int wid = tid >> 5, lid = tid & 31;
    const int wm = wid >> 2, wn = wid & 3;     // warp grid 4(m) x 4(n)
    const int g = lid >> 2, t = lid & 3;

    // chunking: 2080 = 104*14 + 48*13
    const int c = blockIdx.x;
    const int start = 13 * c + min(c, 104);
    const int cnt = 13 + (c < 104 ? 1 : 0);

    int cbi = 0;
    #pragma unroll 1
    while ((cbi + 1) * (129 - (cbi + 1)) / 2 <= start) ++cbi;
    int cbj = cbi + (start - cbi * (129 - cbi) / 2);

    const uint32_t arel = (uint32_t)((wm * 32 + (lid & 15)) * PITCHB + (lid >> 4) * 16);
    const uint32_t brel = (uint32_t)((wn * 32 + (lid >> 4) * 8 + (lid & 7)) * PITCHB
                                     + ((lid >> 3) & 1) * 16);

    // ---- initial loads ----
    load_tile(sb + SMEM_A, cbi, tid);
    load_tile(sb + SMEM_B0, cbj, tid);
    if (tid < 32) {
        cp_async16(sb + SMEM_NI + tid * 16, g_norm + cbi * BM + tid * 4);
        cp_async16(sb + SMEM_NJ0 + tid * 16, g_norm + cbj * BN + tid * 4);
    }
    cp_commit();

    #pragma unroll 1
    for (int it = 0; it < cnt; ++it) {
        const int buf = it & 1;
        const uint32_t bbase = buf ? SMEM_B1 : SMEM_B0;
        const uint32_t njoff = buf ? SMEM_NJ1 : SMEM_NJ0;
        const int row0 = cbi * BM, col0 = cbj * BN;
        const bool isdiag = (cbi == cbj);

        cp_wait<0>();
        __syncthreads();

        // next tile; prefetch its B (+nJ) into the other buffer
        int nbi = cbi, nbj = cbj;
        bool rowchg = false;
        if (it + 1 < cnt) {
            if (cbj == MTILES - 1) { nbi = cbi + 1; nbj = nbi; rowchg = true; }
            else nbj = cbj + 1;
            load_tile(sb + (buf ? SMEM_B0 : SMEM_B1), nbj, tid);
            if (tid < 32)
                cp_async16(sb + (buf ? SMEM_NJ0 : SMEM_NJ1) + tid * 16,
                           g_norm + nbj * BN + tid * 4);
            cp_commit();
        }

        // ---- MMA: warp tile 32x32, K=128 fp8, 4 k-steps of 32 ----
        float acc[2][4][4];
        #pragma unroll
        for (int mt = 0; mt < 2; ++mt)
            #pragma unroll
            for (int nt = 0; nt < 4; ++nt)
                #pragma unroll
                for (int e = 0; e < 4; ++e) acc[mt][nt][e] = 0.0f;

        const uint32_t aA = sb + SMEM_A + arel;
        const uint32_t aB = sb + bbase + brel;

        #pragma unroll
        for (int s = 0; s < 4; ++s) {
            const uint32_t kb = (uint32_t)(s * 32);
            uint32_t a[2][4], b[2][4];
            #pragma unroll
            for (int mt = 0; mt < 2; ++mt)
                ldsm_x4(a[mt], aA + mt * 16 * PITCHB + kb);
            #pragma unroll
            for (int p = 0; p < 2; ++p)
                ldsm_x4(b[p], aB + p * 16 * PITCHB + kb);
            #pragma unroll
            for (int mt = 0; mt < 2; ++mt) {
                mma_fp8(acc[mt][0], a[mt], &b[0][0]);
                mma_fp8(acc[mt][1], a[mt], &b[0][2]);
                mma_fp8(acc[mt][2], a[mt], &b[1][0]);
                mma_fp8(acc[mt][3], a[mt], &b[1][2]);
            }
        }

        // ---- epilogue: sim = rcp(nI + nJ + 1 - 2*dot) ----
        const float* nJs = (const float*)(smem + njoff);
        float rs[2][2], cs[4][2];
        #pragma unroll
        for (int i = 0; i < 2; ++i) rs[i][0] = rs[i][1] = 0.0f;
        #pragma unroll
        for (int i = 0; i < 4; ++i) cs[i][0] = cs[i][1] = 0.0f;

        float cI[2][2], nJ[4][2];
        #pragma unroll
        for (int mt = 0; mt < 2; ++mt) {
            cI[mt][0] = nIs[wm * 32 + mt * 16 + g] + 1.0f;
            cI[mt][1] = nIs[wm * 32 + mt * 16 + g + 8] + 1.0f;
        }
        #pragma unroll
        for (int nt = 0; nt < 4; ++nt) {
            nJ[nt][0] = nJs[wn * 32 + nt * 8 + 2 * t];
            nJ[nt][1] = nJs[wn * 32 + nt * 8 + 2 * t + 1];
        }

        #pragma unroll
        for (int mt = 0; mt < 2; ++mt)
            #pragma unroll
            for (int nt = 0; nt < 4; ++nt)
                #pragma unroll
                for (int r = 0; r < 2; ++r)
                    #pragma unroll
                    for (int e = 0; e < 2; ++e) {
                        float dot = acc[mt][nt][r * 2 + e];
                        float sqp1 = fmaf(-2.0f, dot, cI[mt][r] + nJ[nt][e]);
                        float sim = __fdividef(1.0f, sqp1);
                        if (isdiag) {
                            int li = wm * 32 + mt * 16 + g + r * 8;
                            int lj = wn * 32 + nt * 8 + 2 * t + e;
                            if (li == lj) sim = 1.0f;    // exact self-sim
                        }
                        rs[mt][r] += sim;
                        cs[nt][e] += sim;
                    }

        #pragma unroll
        for (int mt = 0; mt < 2; ++mt)
            #pragma unroll
            for (int r = 0; r < 2; ++r) {
                float v = rs[mt][r];
                v += __shfl_xor_sync(0xffffffffu, v, 1);
                v += __shfl_xor_sync(0xffffffffu, v, 2);
                if (t == 0)
                    atomicAdd(&g_rowsum[row0 + wm * 32 + mt * 16 + g + r * 8], v);
            }
        if (!isdiag) {
            #pragma unroll
            for (int nt = 0; nt < 4; ++nt)
                #pragma unroll
                for (int e = 0; e < 2; ++e) {
                    float v = cs[nt][e];
                    v += __shfl_xor_sync(0xffffffffu, v, 4);
                    v += __shfl_xor_sync(0xffffffffu, v, 8);
                    v += __shfl_xor_sync(0xffffffffu, v, 16);
                    if (g == 0)
                        atomicAdd(&g_rowsum[col0 + wn * 32 + nt * 8 + 2 * t + e], v);
                }
        }

        // row change: reload A + nIs
        if (rowchg) {
            __syncthreads();
            load_tile(sb + SMEM_A, nbi, tid);
            if (tid < 32)
                cp_async16(sb + SMEM_NI + tid * 16, g_norm + nbi * BM + tid * 4);
            cp_commit();
        }
        cbi = nbi; cbj = nbj;
    }
}

// ---------------------------------------------------------------------------
// Kernel 3: final scalar.
// ---------------------------------------------------------------------------
__global__ void finalize_kernel(float* __restrict__ out) {
    __shared__ float sA[1024], s1[1024], s2[1024];
    int tid = threadIdx.x;
    float tA = 0.0f, t1 = 0.0f, t2 = 0.0f;
    for (int i = tid; i < HALF_N; i += 1024) {
        tA += __logf(g_diag[i]);
        t2 += __logf(g_rowsum[i] - 1.0f);
        t1 += __logf(g_rowsum[i + HALF_N] - 1.0f);
    }
    sA[tid] = tA; s1[tid] = t1; s2[tid] = t2;
    __syncthreads();
    for (int s = 512; s; s >>= 1) {
        if (tid < s) {
            sA[tid] += sA[tid + s];
            s1[tid] += s1[tid + s];
            s2[tid] += s2[tid + s];
        }
        __syncthreads();
    }
    if (tid == 0) {
        float align = sA[0] * (1.0f / HALF_N);
        float lse1  = s1[0] * (1.0f / HALF_N);
        float lse2  = s2[0] * (1.0f / HALF_N);
        out[0] = -(align - 0.5f * (lse1 + lse2));
    }
}

// ---------------------------------------------------------------------------
extern "C" void kernel_launch(void* const* d_in, const int* in_sizes, int n_in,
                              void* d_out, int out_size) {
    const float* X = (const float*)d_in[0];
    float* out = (float*)d_out;

    cudaFuncSetAttribute(simsum_kernel,
                         cudaFuncAttributeMaxDynamicSharedMemorySize, SMEM_TOTAL);

    prep_kernel<<<HALF_N / 16, 256>>>(X);     // 2 pairs per warp
    simsum_kernel<<<NCTAS, THREADS, SMEM_TOTAL>>>();
    finalize_kernel<<<1, 1024>>>(out);
}

// round 15
// speedup vs baseline: 1.1774x; 1.1774x over previous
#include <cuda_runtime.h>
#include <cuda_fp16.h>
#include <cuda_fp8.h>
#include <math.h>
#include <stdint.h>

#define N_TOTAL 8192
#define HALF_N  4096
#define BM      128
#define BN      128
#define MTILES  64               // N_TOTAL / BM
#define NCTAS   304              // 2 per SM
#define PITCHB  144              // 128B fp8 row + 16B pad

#define SMEM_A    0
#define SMEM_B0   18432
#define SMEM_B1   36864
#define SMEM_NI   55296
#define SMEM_NJ0  55808
#define SMEM_NJ1  56320
#define SMEM_TOTAL 56832

__device__ __align__(16) uint8_t g_Y[N_TOTAL * 128];   // 1 MB e4m3 copy
__device__ float g_norm[N_TOTAL];
__device__ float g_rowsum[N_TOTAL];
__device__ float g_diag[HALF_N];

// ---------------------------------------------------------------- helpers
__device__ __forceinline__ uint32_t smem_u32(const void* p) {
    uint32_t a;
    asm("{ .reg .u64 t; cvta.to.shared.u64 t, %1; cvt.u32.u64 %0, t; }"
        : "=r"(a) : "l"(p));
    return a;
}
__device__ __forceinline__ void cp_async16(uint32_t dst, const void* src) {
    asm volatile("cp.async.cg.shared.global [%0], [%1], 16;"
                 :: "r"(dst), "l"(src) : "memory");
}
__device__ __forceinline__ void cp_commit() {
    asm volatile("cp.async.commit_group;" ::: "memory");
}
template <int N>
__device__ __forceinline__ void cp_wait() {
    asm volatile("cp.async.wait_group %0;" :: "n"(N) : "memory");
}
__device__ __forceinline__ void mma_fp8(float* c, const uint32_t* a, const uint32_t* b) {
    asm volatile(
        "mma.sync.aligned.m16n8k32.row.col.f32.e4m3.e4m3.f32 "
        "{%0,%1,%2,%3}, {%4,%5,%6,%7}, {%8,%9}, {%0,%1,%2,%3};"
        : "+f"(c[0]), "+f"(c[1]), "+f"(c[2]), "+f"(c[3])
        : "r"(a[0]), "r"(a[1]), "r"(a[2]), "r"(a[3]), "r"(b[0]), "r"(b[1]));
}
__device__ __forceinline__ void ldsm_x4(uint32_t* r, uint32_t addr) {
    asm volatile("ldmatrix.sync.aligned.m8n8.x4.shared.b16 {%0,%1,%2,%3}, [%4];"
                 : "=r"(r[0]), "=r"(r[1]), "=r"(r[2]), "=r"(r[3])
                 : "r"(addr));
}

// ---------------------------------------------------------------------------
// Kernel 1: norms (fp32), diag sims (fp32), rowsum zero, e4m3 pack.
// (round-7 version, 1 pair per warp)
// ---------------------------------------------------------------------------
__global__ void prep_kernel(const float* __restrict__ X) {
    int warp = (blockIdx.x * blockDim.x + threadIdx.x) >> 5;
    int lane = threadIdx.x & 31;
    if (warp >= N_TOTAL) return;
    const float4* X4 = (const float4*)X;

    float4 v = X4[warp * 32 + lane];
    float s = v.x * v.x + v.y * v.y + v.z * v.z + v.w * v.w;
    #pragma unroll
    for (int off = 16; off; off >>= 1) s += __shfl_xor_sync(0xffffffffu, s, off);
    if (lane == 0) { g_norm[warp] = s; g_rowsum[warp] = 0.0f; }

    uint32_t b0 = __nv_cvt_float_to_fp8(v.x, __NV_SATFINITE, __NV_E4M3);
    uint32_t b1 = __nv_cvt_float_to_fp8(v.y, __NV_SATFINITE, __NV_E4M3);
    uint32_t b2 = __nv_cvt_float_to_fp8(v.z, __NV_SATFINITE, __NV_E4M3);
    uint32_t b3 = __nv_cvt_float_to_fp8(v.w, __NV_SATFINITE, __NV_E4M3);
    ((uint32_t*)(g_Y + (size_t)warp * 128))[lane] =
        b0 | (b1 << 8) | (b2 << 16) | (b3 << 24);

    if (warp < HALF_N) {
        float4 w = X4[(warp + HALF_N) * 32 + lane];
        float dx = v.x - w.x, dy = v.y - w.y, dz = v.z - w.z, dw = v.w - w.w;
        float sq = dx * dx + dy * dy + dz * dz + dw * dw;
        #pragma unroll
        for (int off = 16; off; off >>= 1) sq += __shfl_xor_sync(0xffffffffu, sq, off);
        if (lane == 0) g_diag[warp] = 1.0f / (fmaxf(sq, 0.0f) + 1.0f);
    }
}

// ---------------------------------------------------------------------------
// Kernel 2: round-7 persistent triangular fp8 GEMM; only change: the
// diagonal handling is hoisted OUT of the element loop (two epilogue bodies).
// ---------------------------------------------------------------------------
__global__ void __launch_bounds__(256, 2)
simsum_kernel() {
    extern __shared__ char smem[];
    const uint32_t sb = smem_u32(smem);
    float* nIs = (float*)(smem + SMEM_NI);

    const int tid = threadIdx.x;
    const int wid = tid >> 5, lid = tid & 31;
    const int wm = wid >> 2, wn = wid & 3;     // warp grid 2x4
    const int g = lid >> 2, t = lid & 3;

    const int c = blockIdx.x;
    const int start = 6 * c + min(c, 256);     // 2080 = 256*7 + 48*6
    const int cnt = 6 + (c < 256 ? 1 : 0);

    int cbi = 0;
    #pragma unroll 1
    while ((cbi + 1) * (129 - (cbi + 1)) / 2 <= start) ++cbi;
    int cbj = cbi + (start - cbi * (129 - cbi) / 2);

    const uint32_t arel = (uint32_t)((wm * 64 + (lid & 15)) * PITCHB + (lid >> 4) * 16);
    const uint32_t brel = (uint32_t)((wn * 32 + (lid >> 4) * 8 + (lid & 7)) * PITCHB
                                     + ((lid >> 3) & 1) * 16);

    // ---- initial loads: A(cbi), nIs, B0(cbj), nJ0 ----
    {
        const char* Yb = (const char*)g_Y;
        #pragma unroll
        for (int it = 0; it < 4; ++it) {
            int chunk = it * 256 + tid;
            int r = chunk >> 3, cc = chunk & 7;
            cp_async16(sb + SMEM_A + r * PITCHB + cc * 16,
                       Yb + (size_t)(cbi * BM + r) * 128 + cc * 16);
            cp_async16(sb + SMEM_B0 + r * PITCHB + cc * 16,
                       Yb + (size_t)(cbj * BN + r) * 128 + cc * 16);
        }
        if (tid < 32) {
            cp_async16(sb + SMEM_NI + tid * 16, g_norm + cbi * BM + tid * 4);
            cp_async16(sb + SMEM_NJ0 + tid * 16, g_norm + cbj * BN + tid * 4);
        }
        cp_commit();
    }

    #pragma unroll 1
    for (int it = 0; it < cnt; ++it) {
        const int buf = it & 1;
        const uint32_t bbase = buf ? SMEM_B1 : SMEM_B0;
        const uint32_t njoff = buf ? SMEM_NJ1 : SMEM_NJ0;
        const int row0 = cbi * BM, col0 = cbj * BN;
        const bool isdiag = (cbi == cbj);

        cp_wait<0>();
        __syncthreads();

        // next tile indices; prefetch its B (+nJ) into the other buffer
        int nbi = cbi, nbj = cbj;
        bool rowchg = false;
        if (it + 1 < cnt) {
            if (cbj == MTILES - 1) { nbi = cbi + 1; nbj = nbi; rowchg = true; }
            else nbj = cbj + 1;
            const uint32_t nb = buf ? SMEM_B0 : SMEM_B1;
            const char* Yb = (const char*)g_Y;
            #pragma unroll
            for (int i2 = 0; i2 < 4; ++i2) {
                int chunk = i2 * 256 + tid;
                int r = chunk >> 3, cc = chunk & 7;
                cp_async16(sb + nb + r * PITCHB + cc * 16,
                           Yb + (size_t)(nbj * BN + r) * 128 + cc * 16);
            }
            if (tid < 32)
                cp_async16(sb + (buf ? SMEM_NJ0 : SMEM_NJ1) + tid * 16,
                           g_norm + nbj * BN + tid * 4);
            cp_commit();
        }

        // ---- MMA: 128x128, K=128 fp8, 4 k-steps of 32 ----
        float acc[4][4][4];
        #pragma unroll
        for (int mt = 0; mt < 4; ++mt)
            #pragma unroll
            for (int nt = 0; nt < 4; ++nt)
                #pragma unroll
                for (int e = 0; e < 4; ++e) acc[mt][nt][e] = 0.0f;

        const uint32_t aA = sb + SMEM_A + arel;
        const uint32_t aB = sb + bbase + brel;

        #pragma unroll
        for (int s = 0; s < 4; ++s) {
            const uint32_t kb = (uint32_t)(s * 32);
            uint32_t a[4][4], b[2][4];
            #pragma unroll
            for (int mt = 0; mt < 4; ++mt)
                ldsm_x4(a[mt], aA + mt * 16 * PITCHB + kb);
            #pragma unroll
            for (int p = 0; p < 2; ++p)
                ldsm_x4(b[p], aB + p * 16 * PITCHB + kb);
            #pragma unroll
            for (int mt = 0; mt < 4; ++mt) {
                mma_fp8(acc[mt][0], a[mt], &b[0][0]);
                mma_fp8(acc[mt][1], a[mt], &b[0][2]);
                mma_fp8(acc[mt][2], a[mt], &b[1][0]);
                mma_fp8(acc[mt][3], a[mt], &b[1][2]);
            }
        }

        // ---- epilogue: sim = rcp(nI + nJ + 1 - 2*dot) -----------------------
        const float* nJs = (const float*)(smem + njoff);
        float rs[4][2], cs[4][2];
        #pragma unroll
        for (int i = 0; i < 4; ++i) rs[i][0] = rs[i][1] = 0.0f;
        #pragma unroll
        for (int i = 0; i < 4; ++i) cs[i][0] = cs[i][1] = 0.0f;

        float cI[4][2], nJ[4][2];
        #pragma unroll
        for (int mt = 0; mt < 4; ++mt) {
            cI[mt][0] = nIs[wm * 64 + mt * 16 + g] + 1.0f;
            cI[mt][1] = nIs[wm * 64 + mt * 16 + g + 8] + 1.0f;
        }
        #pragma unroll
        for (int nt = 0; nt < 4; ++nt) {
            nJ[nt][0] = nJs[wn * 32 + nt * 8 + 2 * t];
            nJ[nt][1] = nJs[wn * 32 + nt * 8 + 2 * t + 1];
        }

        if (!isdiag) {
            // HOT PATH (2016/2080 tiles): no index math, no compares.
            #pragma unroll
            for (int mt = 0; mt < 4; ++mt)
                #pragma unroll
                for (int nt = 0; nt < 4; ++nt)
                    #pragma unroll
                    for (int r = 0; r < 2; ++r)
                        #pragma unroll
                        for (int e = 0; e < 2; ++e) {
                            float dot = acc[mt][nt][r * 2 + e];
                            float sqp1 = fmaf(-2.0f, dot, cI[mt][r] + nJ[nt][e]);
                            float sim = __fdividef(1.0f, sqp1);
                            rs[mt][r] += sim;
                            cs[nt][e] += sim;
                        }
        } else {
            // DIAG PATH (64 tiles): exact self-sim override.
            #pragma unroll
            for (int mt = 0; mt < 4; ++mt)
                #pragma unroll
                for (int nt = 0; nt < 4; ++nt)
                    #pragma unroll
                    for (int r = 0; r < 2; ++r)
                        #pragma unroll
                        for (int e = 0; e < 2; ++e) {
                            float dot = acc[mt][nt][r * 2 + e];
                            float sqp1 = fmaf(-2.0f, dot, cI[mt][r] + nJ[nt][e]);
                            float sim = __fdividef(1.0f, sqp1);
                            int li = wm * 64 + mt * 16 + g + r * 8;
                            int lj = wn * 32 + nt * 8 + 2 * t + e;
                            if (li == lj) sim = 1.0f;    // exact self-sim
                            rs[mt][r] += sim;
                            cs[nt][e] += sim;
                        }
        }

        #pragma unroll
        for (int mt = 0; mt < 4; ++mt)
            #pragma unroll
            for (int r = 0; r < 2; ++r) {
                float v = rs[mt][r];
                v += __shfl_xor_sync(0xffffffffu, v, 1);
                v += __shfl_xor_sync(0xffffffffu, v, 2);
                if (t == 0)
                    atomicAdd(&g_rowsum[row0 + wm * 64 + mt * 16 + g + r * 8], v);
            }
        if (!isdiag) {
            #pragma unroll
            for (int nt = 0; nt < 4; ++nt)
                #pragma unroll
                for (int e = 0; e < 2; ++e) {
                    float v = cs[nt][e];
                    v += __shfl_xor_sync(0xffffffffu, v, 4);
                    v += __shfl_xor_sync(0xffffffffu, v, 8);
                    v += __shfl_xor_sync(0xffffffffu, v, 16);
                    if (g == 0)
                        atomicAdd(&g_rowsum[col0 + wn * 32 + nt * 8 + 2 * t + e], v);
                }
        }

        // row change: reload A + nIs (after all warps are done with old A)
        if (rowchg) {
            __syncthreads();
            const char* Yb = (const char*)g_Y;
            #pragma unroll
            for (int i2 = 0; i2 < 4; ++i2) {
                int chunk = i2 * 256 + tid;
                int r = chunk >> 3, cc = chunk & 7;
                cp_async16(sb + SMEM_A + r * PITCHB + cc * 16,
                           Yb + (size_t)(nbi * BM + r) * 128 + cc * 16);
            }
            if (tid < 32)
                cp_async16(sb + SMEM_NI + tid * 16, g_norm + nbi * BM + tid * 4);
            cp_commit();
        }
        cbi = nbi; cbj = nbj;
    }
}

// ---------------------------------------------------------------------------
// Kernel 3: final scalar.
// ---------------------------------------------------------------------------
__global__ void finalize_kernel(float* __restrict__ out) {
    __shared__ float sA[1024], s1[1024], s2[1024];
    int tid = threadIdx.x;
    float tA = 0.0f, t1 = 0.0f, t2 = 0.0f;
    for (int i = tid; i < HALF_N; i += 1024) {
        tA += __logf(g_diag[i]);
        t2 += __logf(g_rowsum[i] - 1.0f);
        t1 += __logf(g_rowsum[i + HALF_N] - 1.0f);
    }
    sA[tid] = tA; s1[tid] = t1; s2[tid] = t2;
    __syncthreads();
    for (int s = 512; s; s >>= 1) {
        if (tid < s) {
            sA[tid] += sA[tid + s];
            s1[tid] += s1[tid + s];
            s2[tid] += s2[tid + s];
        }
        __syncthreads();
    }
    if (tid == 0) {
        float align = sA[0] * (1.0f / HALF_N);
        float lse1  = s1[0] * (1.0f / HALF_N);
        float lse2  = s2[0] * (1.0f / HALF_N);
        out[0] = -(align - 0.5f * (lse1 + lse2));
    }
}

// ---------------------------------------------------------------------------
extern "C" void kernel_launch(void* const* d_in, const int* in_sizes, int n_in,
                              void* d_out, int out_size) {
    const float* X = (const float*)d_in[0];
    float* out = (float*)d_out;

    cudaFuncSetAttribute(simsum_kernel,
                         cudaFuncAttributeMaxDynamicSharedMemorySize, SMEM_TOTAL);

    prep_kernel<<<N_TOTAL / 8, 256>>>(X);
    simsum_kernel<<<NCTAS, 256, SMEM_TOTAL>>>();
    finalize_kernel<<<1, 1024>>>(out);
}